// round 11
// baseline (speedup 1.0000x reference)
#include <cuda_runtime.h>
#include <cuda_fp16.h>
#include <cstdint>

#define NT      17
#define DIN     128
#define NNODES  32768
#define ROWS    128
#define MAXWORK 274

#define A_STRIDE_H 136            // A tile stride in halves (272B)
#define W_STRIDE_U 136            // W k2-row stride in u32
#define W_TERM_U   (64 * W_STRIDE_U)   // 8704 u32 per term

// smem byte offsets
#define OFF_ROWIDX 0
#define OFF_B1     512
#define OFF_B2     1024
#define OFF_A      1536                    // 128*272 = 34816
#define OFF_W      (OFF_A + 34816)
#define SMEM_BYTES (OFF_W + 2 * W_TERM_U * 4)   // 105984

#define WELEMS (NT * 64 * 128)    // 139264

// ---------------- allocation-free scratch ----------------
__device__ int g_count[NT];
__device__ int g_idx[NT * NNODES];
__device__ uint32_t g_w[2][NT][2][8192];

// ---------------- helpers ----------------
__device__ __forceinline__ uint32_t smem_u32(const void* p) {
    uint32_t a;
    asm("{ .reg .u64 t; cvta.to.shared.u64 t, %1; cvt.u32.u64 %0, t; }" : "=r"(a) : "l"(p));
    return a;
}

__device__ __forceinline__ void cp16(uint32_t dst, const void* src) {
    asm volatile("cp.async.cg.shared.global [%0], [%1], 16;" :: "r"(dst), "l"(src));
}

__device__ __forceinline__ void ldsm4(uint32_t* r, uint32_t addr) {
    asm volatile("ldmatrix.sync.aligned.m8n8.x4.shared.b16 {%0,%1,%2,%3}, [%4];"
                 : "=r"(r[0]), "=r"(r[1]), "=r"(r[2]), "=r"(r[3]) : "r"(addr));
}

__device__ __forceinline__ void mma_f16(float* c, const uint32_t* a, uint32_t b0, uint32_t b1) {
    asm volatile(
        "mma.sync.aligned.m16n8k16.row.col.f32.f16.f16.f32 "
        "{%0,%1,%2,%3}, {%4,%5,%6,%7}, {%8,%9}, {%0,%1,%2,%3};"
        : "+f"(c[0]), "+f"(c[1]), "+f"(c[2]), "+f"(c[3])
        : "r"(a[0]), "r"(a[1]), "r"(a[2]), "r"(a[3]), "r"(b0), "r"(b1));
}

__device__ __forceinline__ uint32_t packh2(__half a, __half b) {
    __half2 h = __halves2half2(a, b);
    return *reinterpret_cast<uint32_t*>(&h);
}

// ---------------- prep ----------------
__global__ void prep_kernel(const float* __restrict__ W1, const float* __restrict__ W2) {
    if (blockIdx.x == 0 && threadIdx.x < NT) g_count[threadIdx.x] = 0;
    int idx = blockIdx.x * 256 + threadIdx.x;
    int t   = idx >> 13;
    int rem = idx & 8191;
    size_t off = (size_t)t * 16384 + (size_t)(rem >> 7) * 256 + (rem & 127);
    {
        float a0 = __ldg(W1 + off), a1 = __ldg(W1 + off + 128);
        __half h0 = __float2half_rn(a0), h1 = __float2half_rn(a1);
        __half l0 = __float2half_rn(a0 - __half2float(h0));
        __half l1 = __float2half_rn(a1 - __half2float(h1));
        g_w[0][t][0][rem] = packh2(h0, h1);
        g_w[0][t][1][rem] = packh2(l0, l1);
    }
    {
        float a0 = __ldg(W2 + off), a1 = __ldg(W2 + off + 128);
        __half h0 = __float2half_rn(a0), h1 = __float2half_rn(a1);
        __half l0 = __float2half_rn(a0 - __half2float(h0));
        __half l1 = __float2half_rn(a1 - __half2float(h1));
        g_w[1][t][0][rem] = packh2(h0, h1);
        g_w[1][t][1][rem] = packh2(l0, l1);
    }
}

// ---------------- two-level scatter ----------------
__global__ void scatter_kernel(const int* __restrict__ types) {
    __shared__ int scount[NT];
    __shared__ int sbase_[NT];
    int tid = threadIdx.x;
    if (tid < NT) scount[tid] = 0;
    __syncthreads();
    int n = blockIdx.x * blockDim.x + tid;
    int t = types[n];
    int rank = atomicAdd(&scount[t], 1);
    __syncthreads();
    if (tid < NT) sbase_[tid] = atomicAdd(&g_count[tid], scount[tid]);
    __syncthreads();
    g_idx[t * NNODES + sbase_[t] + rank] = n;
}

// ---------------- W staging via cp.async (512 threads) ----------------
__device__ __forceinline__ void stage_w(int layer, int t, int tid, uint32_t wsm) {
    #pragma unroll
    for (int i = 0; i < 8; i++) {
        int li   = tid + i * 512;        // 0..4095
        int term = li >> 11;
        int r    = (li >> 5) & 63;
        int seg  = li & 31;
        uint32_t dst = wsm + term * (W_TERM_U * 4) + r * (W_STRIDE_U * 4) + seg * 16;
        const char* src = reinterpret_cast<const char*>(g_w[layer][t][term]) + r * 512 + seg * 16;
        cp16(dst, src);
    }
    asm volatile("cp.async.commit_group;" ::: "memory");
}

// ---------------- fp16 2-term GEMM, warp tile 32x32 ----------------
__device__ __forceinline__ void run_gemm(uint32_t sbase, const uint32_t* __restrict__ Wsm,
                                         float acc[2][4][4], int lane, int mbase, int nbase) {
    int rowA = mbase + ((lane >> 3) & 1) * 8 + (lane & 7);
    uint32_t aAddr = sbase + OFF_A + rowA * (A_STRIDE_H * 2) + (lane >> 4) * 16;
    const int li = lane & 3;
    const int cb = nbase + (lane >> 2);

    #pragma unroll 1
    for (int kc = 0; kc < 8; kc++) {
        uint32_t a0[4], a1[4];
        ldsm4(a0, aAddr + kc * 32);
        ldsm4(a1, aAddr + 16 * (A_STRIDE_H * 2) + kc * 32);
        int k2b = kc * 8 + li;
        const uint32_t* Wh = Wsm + k2b * W_STRIDE_U + cb;
        const uint32_t* Wl = Wh + W_TERM_U;
        #pragma unroll
        for (int nt = 0; nt < 4; nt++) {
            uint32_t b0 = Wh[nt * 8];
            uint32_t b1 = Wh[nt * 8 + 4 * W_STRIDE_U];
            mma_f16(acc[0][nt], a0, b0, b1);
            mma_f16(acc[1][nt], a1, b0, b1);
            b0 = Wl[nt * 8];
            b1 = Wl[nt * 8 + 4 * W_STRIDE_U];
            mma_f16(acc[0][nt], a0, b0, b1);
            mma_f16(acc[1][nt], a1, b0, b1);
        }
    }
}

extern __shared__ __align__(16) char smem[];

__global__ __launch_bounds__(512, 2) void mlp_kernel(
    const float* __restrict__ x,
    const float* __restrict__ b1,
    const float* __restrict__ b2,
    float* __restrict__ out)
{
    // derive (type, tile) from counts — no worklist
    int w = blockIdx.x;
    int t = 0;
    int cnt = 0;
    #pragma unroll 1
    for (; t < NT; t++) {
        cnt = g_count[t];
        int tiles = (cnt + ROWS - 1) / ROWS;
        if (w < tiles) break;
        w -= tiles;
    }
    if (t >= NT) return;
    const int base = w * ROWS;

    const uint32_t sbase = smem_u32(smem);
    const int tid  = threadIdx.x;
    const int lane = tid & 31;
    const int warp = tid >> 5;
    const int mbase = (warp >> 2) * 32;
    const int nbase = (warp & 3) * 32;

    int*   rowidx = reinterpret_cast<int*>(smem + OFF_ROWIDX);
    float* sB1    = reinterpret_cast<float*>(smem + OFF_B1);
    float* sB2    = reinterpret_cast<float*>(smem + OFF_B2);
    const uint32_t* Wsm = reinterpret_cast<const uint32_t*>(smem + OFF_W);

    stage_w(0, t, tid, sbase + OFF_W);      // async W1 copy under gather

    if (tid < ROWS) {
        int r = base + tid;
        rowidx[tid] = (r < cnt) ? g_idx[t * NNODES + r] : -1;
        sB1[tid] = __ldg(b1 + t * DIN + tid);
        sB2[tid] = __ldg(b2 + t * DIN + tid);
    }
    __syncthreads();

    // Gather x rows -> fp16 A tile. thread = (row = tid/4, quarter = tid&3).
    {
        int r = tid >> 2, q = tid & 3;
        int g = rowidx[r];
        uint32_t* dst = reinterpret_cast<uint32_t*>(smem + OFF_A + r * (A_STRIDE_H * 2) + q * 64);
        if (g >= 0) {
            const float4* src = reinterpret_cast<const float4*>(x + (size_t)g * DIN + q * 32);
            #pragma unroll
            for (int i = 0; i < 8; i++) {
                float4 v = __ldg(src + i);
                __half2 p0 = __floats2half2_rn(v.x, v.y);
                __half2 p1 = __floats2half2_rn(v.z, v.w);
                dst[2 * i]     = *reinterpret_cast<uint32_t*>(&p0);
                dst[2 * i + 1] = *reinterpret_cast<uint32_t*>(&p1);
            }
        } else {
            #pragma unroll
            for (int i = 0; i < 16; i++) dst[i] = 0u;
        }
    }

    asm volatile("cp.async.wait_group 0;" ::: "memory");
    __syncthreads();

    float acc[2][4][4];
    #pragma unroll
    for (int s = 0; s < 2; s++)
        #pragma unroll
        for (int nt = 0; nt < 4; nt++)
            #pragma unroll
            for (int i = 0; i < 4; i++) acc[s][nt][i] = 0.f;

    // ---------------- Layer 1 ----------------
    run_gemm(sbase, Wsm, acc, lane, mbase, nbase);

    __syncthreads();
    stage_w(1, t, tid, sbase + OFF_W);      // overlap W2 copy with epilogue

    #pragma unroll
    for (int s = 0; s < 2; s++) {
        #pragma unroll
        for (int nt = 0; nt < 4; nt++) {
            int col = nbase + nt * 8 + 2 * (lane & 3);
            float bb0 = sB1[col], bb1 = sB1[col + 1];
            int r0 = mbase + s * 16 + (lane >> 2);
            __half2 v0 = __floats2half2_rn(fmaxf(acc[s][nt][0] + bb0, 0.f),
                                           fmaxf(acc[s][nt][1] + bb1, 0.f));
            __half2 v1 = __floats2half2_rn(fmaxf(acc[s][nt][2] + bb0, 0.f),
                                           fmaxf(acc[s][nt][3] + bb1, 0.f));
            *reinterpret_cast<__half2*>(smem + OFF_A + r0 * (A_STRIDE_H * 2) + col * 2) = v0;
            *reinterpret_cast<__half2*>(smem + OFF_A + (r0 + 8) * (A_STRIDE_H * 2) + col * 2) = v1;
            acc[s][nt][0] = acc[s][nt][1] = acc[s][nt][2] = acc[s][nt][3] = 0.f;
        }
    }

    asm volatile("cp.async.wait_group 0;" ::: "memory");
    __syncthreads();

    // ---------------- Layer 2 ----------------
    run_gemm(sbase, Wsm, acc, lane, mbase, nbase);

    #pragma unroll
    for (int s = 0; s < 2; s++) {
        #pragma unroll
        for (int nt = 0; nt < 4; nt++) {
            int col = nbase + nt * 8 + 2 * (lane & 3);
            float bb0 = sB2[col], bb1 = sB2[col + 1];
            int r0 = mbase + s * 16 + (lane >> 2);
            int g0 = rowidx[r0];
            int g1 = rowidx[r0 + 8];
            if (g0 >= 0)
                *reinterpret_cast<float2*>(out + (size_t)g0 * DIN + col) =
                    make_float2(acc[s][nt][0] + bb0, acc[s][nt][1] + bb1);
            if (g1 >= 0)
                *reinterpret_cast<float2*>(out + (size_t)g1 * DIN + col) =
                    make_float2(acc[s][nt][2] + bb0, acc[s][nt][3] + bb1);
        }
    }
}

extern "C" void kernel_launch(void* const* d_in, const int* in_sizes, int n_in,
                              void* d_out, int out_size)
{
    const float* x     = (const float*)d_in[0];
    const float* W1    = (const float*)d_in[1];
    const float* b1    = (const float*)d_in[2];
    const float* W2    = (const float*)d_in[3];
    const float* b2    = (const float*)d_in[4];
    const int*   types = (const int*)  d_in[5];
    float*       out   = (float*)d_out;

    cudaFuncSetAttribute(mlp_kernel, cudaFuncAttributeMaxDynamicSharedMemorySize, SMEM_BYTES);

    prep_kernel<<<WELEMS / 256, 256>>>(W1, W2);
    scatter_kernel<<<NNODES / 256, 256>>>(types);
    mlp_kernel<<<MAXWORK, 512, SMEM_BYTES>>>(x, b1, b2, out);
}

// round 12
// speedup vs baseline: 1.4502x; 1.4502x over previous
#include <cuda_runtime.h>
#include <cuda_fp16.h>
#include <cstdint>

#define NT      17
#define DIN     128
#define NNODES  32768
#define ROWS    128
#define MAXWORK 274

#define A_STRIDE_H 136            // A tile stride in halves (272B) — LDSM conflict-free
#define WP_STRIDE  264            // pair-packed W row stride in u32 (264%32==8 -> conflict-free LDS.64)
#define WP_TERM_U  (32 * WP_STRIDE)     // 8448 u32 per term (8 kc x 4 li rows)
#define WP_LAYER_U (2 * WP_TERM_U)      // 16896 u32 per layer (hi + lo)
#define WP_CHUNKS  (WP_LAYER_U / 4)     // 4224 16B chunks per layer

// smem byte offsets
#define OFF_ROWIDX 0
#define OFF_B1     512
#define OFF_B2     1024
#define OFF_A      1536                    // 128*272 = 34816
#define OFF_W      (OFF_A + 34816)         // 36352
#define SMEM_BYTES (OFF_W + WP_LAYER_U * 4)   // 103936

#define WELEMS (NT * 64 * 128)    // 139264

// ---------------- allocation-free scratch ----------------
__device__ int g_count[NT];
__device__ int g_idx[NT * NNODES];
// Pair-packed fp16x2 W: [layer][type][ hi:0..8447 | lo:8448..16895 ]
// index = (kc*4+li)*264 + col*2 + j ; entry = pack(W[2*k2][col], W[2*k2+1][col]),
// k2 = kc*8 + li + 4*j
__device__ uint32_t g_w[2][NT][WP_LAYER_U];

// ---------------- helpers ----------------
__device__ __forceinline__ uint32_t smem_u32(const void* p) {
    uint32_t a;
    asm("{ .reg .u64 t; cvta.to.shared.u64 t, %1; cvt.u32.u64 %0, t; }" : "=r"(a) : "l"(p));
    return a;
}

__device__ __forceinline__ void cp16(uint32_t dst, const void* src) {
    asm volatile("cp.async.cg.shared.global [%0], [%1], 16;" :: "r"(dst), "l"(src));
}

__device__ __forceinline__ void ldsm4(uint32_t* r, uint32_t addr) {
    asm volatile("ldmatrix.sync.aligned.m8n8.x4.shared.b16 {%0,%1,%2,%3}, [%4];"
                 : "=r"(r[0]), "=r"(r[1]), "=r"(r[2]), "=r"(r[3]) : "r"(addr));
}

__device__ __forceinline__ void mma_f16(float* c, const uint32_t* a, uint32_t b0, uint32_t b1) {
    asm volatile(
        "mma.sync.aligned.m16n8k16.row.col.f32.f16.f16.f32 "
        "{%0,%1,%2,%3}, {%4,%5,%6,%7}, {%8,%9}, {%0,%1,%2,%3};"
        : "+f"(c[0]), "+f"(c[1]), "+f"(c[2]), "+f"(c[3])
        : "r"(a[0]), "r"(a[1]), "r"(a[2]), "r"(a[3]), "r"(b0), "r"(b1));
}

__device__ __forceinline__ uint32_t packh2(__half a, __half b) {
    __half2 h = __halves2half2(a, b);
    return *reinterpret_cast<uint32_t*>(&h);
}

// ---------------- prep: zero counts + pair-packed fp16 hi/lo split ----------------
__global__ void prep_kernel(const float* __restrict__ W1, const float* __restrict__ W2) {
    if (blockIdx.x == 0 && threadIdx.x < NT) g_count[threadIdx.x] = 0;
    int idx = blockIdx.x * 256 + threadIdx.x;   // grid = WELEMS/256 = 544, exact
    int t    = idx >> 13;
    int rem  = idx & 8191;
    int k2   = rem >> 7;
    int col  = rem & 127;
    int kc = k2 >> 3, r = k2 & 7, li = r & 3, j = r >> 2;
    int pidx = (kc * 4 + li) * WP_STRIDE + col * 2 + j;
    size_t off = (size_t)t * 16384 + (size_t)k2 * 256 + col;
    {
        float a0 = __ldg(W1 + off), a1 = __ldg(W1 + off + 128);
        __half h0 = __float2half_rn(a0), h1 = __float2half_rn(a1);
        __half l0 = __float2half_rn(a0 - __half2float(h0));
        __half l1 = __float2half_rn(a1 - __half2float(h1));
        g_w[0][t][pidx] = packh2(h0, h1);
        g_w[0][t][WP_TERM_U + pidx] = packh2(l0, l1);
    }
    {
        float a0 = __ldg(W2 + off), a1 = __ldg(W2 + off + 128);
        __half h0 = __float2half_rn(a0), h1 = __float2half_rn(a1);
        __half l0 = __float2half_rn(a0 - __half2float(h0));
        __half l1 = __float2half_rn(a1 - __half2float(h1));
        g_w[1][t][pidx] = packh2(h0, h1);
        g_w[1][t][WP_TERM_U + pidx] = packh2(l0, l1);
    }
}

// ---------------- two-level scatter ----------------
__global__ void scatter_kernel(const int* __restrict__ types) {
    __shared__ int scount[NT];
    __shared__ int sbase_[NT];
    int tid = threadIdx.x;
    if (tid < NT) scount[tid] = 0;
    __syncthreads();
    int n = blockIdx.x * blockDim.x + tid;
    int t = types[n];
    int rank = atomicAdd(&scount[t], 1);
    __syncthreads();
    if (tid < NT) sbase_[tid] = atomicAdd(&g_count[tid], scount[tid]);
    __syncthreads();
    g_idx[t * NNODES + sbase_[t] + rank] = n;
}

// ---------------- W staging: linear cp.async copy of one layer ----------------
__device__ __forceinline__ void stage_w(int layer, int t, int tid, uint32_t wsm) {
    const char* src = reinterpret_cast<const char*>(g_w[layer][t]);
    #pragma unroll
    for (int i = 0; i < 17; i++) {
        int li = tid + i * 256;
        if (li < WP_CHUNKS) cp16(wsm + li * 16, src + li * 16);
    }
    asm volatile("cp.async.commit_group;" ::: "memory");
}

// ---------------- fp16 2-term GEMM, warp tile 32x64, A-prefetch ----------------
__device__ __forceinline__ void run_gemm(uint32_t sbase, const uint32_t* __restrict__ Wsm,
                                         float acc[2][8][4], int lane, int mbase, int nbase) {
    int rowA = mbase + ((lane >> 3) & 1) * 8 + (lane & 7);
    uint32_t aAddr = sbase + OFF_A + rowA * (A_STRIDE_H * 2) + (lane >> 4) * 16;
    const int li = lane & 3;
    const int cb2 = (nbase + (lane >> 2)) * 2;

    uint32_t a0[4], a1[4];
    ldsm4(a0, aAddr);
    ldsm4(a1, aAddr + 16 * (A_STRIDE_H * 2));

    #pragma unroll 2
    for (int kc = 0; kc < 8; kc++) {
        uint32_t n0[4], n1[4];
        if (kc < 7) {
            ldsm4(n0, aAddr + (kc + 1) * 32);
            ldsm4(n1, aAddr + 16 * (A_STRIDE_H * 2) + (kc + 1) * 32);
        }
        const uint32_t* Wh = Wsm + (kc * 4 + li) * WP_STRIDE + cb2;
        const uint32_t* Wl = Wh + WP_TERM_U;
        #pragma unroll
        for (int nt = 0; nt < 8; nt++) {
            uint2 bh = *reinterpret_cast<const uint2*>(Wh + nt * 16);
            uint2 bl = *reinterpret_cast<const uint2*>(Wl + nt * 16);
            mma_f16(acc[0][nt], a0, bh.x, bh.y);
            mma_f16(acc[1][nt], a1, bh.x, bh.y);
            mma_f16(acc[0][nt], a0, bl.x, bl.y);
            mma_f16(acc[1][nt], a1, bl.x, bl.y);
        }
        #pragma unroll
        for (int i = 0; i < 4; i++) { a0[i] = n0[i]; a1[i] = n1[i]; }
    }
}

extern __shared__ __align__(16) char smem[];

__global__ __launch_bounds__(256, 2) void mlp_kernel(
    const float* __restrict__ x,
    const float* __restrict__ b1,
    const float* __restrict__ b2,
    float* __restrict__ out)
{
    // derive (type, tile) from counts — no worklist
    int w = blockIdx.x;
    int t = 0;
    int cnt = 0;
    #pragma unroll 1
    for (; t < NT; t++) {
        cnt = g_count[t];
        int tiles = (cnt + ROWS - 1) / ROWS;
        if (w < tiles) break;
        w -= tiles;
    }
    if (t >= NT) return;
    const int base = w * ROWS;

    const uint32_t sbase = smem_u32(smem);
    const int tid  = threadIdx.x;
    const int lane = tid & 31;
    const int warp = tid >> 5;
    const int mbase = (warp >> 1) * 32;
    const int nbase = (warp & 1) * 64;

    int*   rowidx = reinterpret_cast<int*>(smem + OFF_ROWIDX);
    float* sB1    = reinterpret_cast<float*>(smem + OFF_B1);
    float* sB2    = reinterpret_cast<float*>(smem + OFF_B2);
    const uint32_t* Wsm = reinterpret_cast<const uint32_t*>(smem + OFF_W);

    stage_w(0, t, tid, sbase + OFF_W);      // async W1 copy under gather

    if (tid < ROWS) {
        int r = base + tid;
        rowidx[tid] = (r < cnt) ? g_idx[t * NNODES + r] : -1;
        sB1[tid] = __ldg(b1 + t * DIN + tid);
        sB2[tid] = __ldg(b2 + t * DIN + tid);
    }
    __syncthreads();

    // Gather x rows -> fp16 A tile. thread = (row = tid/2, k-half = tid&1).
    {
        int r = tid >> 1, kh = tid & 1;
        int g = rowidx[r];
        uint32_t* dst = reinterpret_cast<uint32_t*>(smem + OFF_A + r * (A_STRIDE_H * 2) + kh * 128);
        if (g >= 0) {
            const float4* src = reinterpret_cast<const float4*>(x + (size_t)g * DIN + kh * 64);
            #pragma unroll
            for (int i = 0; i < 16; i++) {
                float4 v = __ldg(src + i);
                __half2 p0 = __floats2half2_rn(v.x, v.y);
                __half2 p1 = __floats2half2_rn(v.z, v.w);
                dst[2 * i]     = *reinterpret_cast<uint32_t*>(&p0);
                dst[2 * i + 1] = *reinterpret_cast<uint32_t*>(&p1);
            }
        } else {
            #pragma unroll
            for (int i = 0; i < 32; i++) dst[i] = 0u;
        }
    }

    asm volatile("cp.async.wait_group 0;" ::: "memory");
    __syncthreads();

    float acc[2][8][4];
    #pragma unroll
    for (int s = 0; s < 2; s++)
        #pragma unroll
        for (int nt = 0; nt < 8; nt++)
            #pragma unroll
            for (int i = 0; i < 4; i++) acc[s][nt][i] = 0.f;

    // ---------------- Layer 1 ----------------
    run_gemm(sbase, Wsm, acc, lane, mbase, nbase);

    __syncthreads();                    // gemm1 done reading W + A
    stage_w(1, t, tid, sbase + OFF_W);  // overlap W2 copy with epilogue

    #pragma unroll
    for (int s = 0; s < 2; s++) {
        #pragma unroll
        for (int nt = 0; nt < 8; nt++) {
            int col = nbase + nt * 8 + 2 * (lane & 3);
            float bb0 = sB1[col], bb1 = sB1[col + 1];
            int r0 = mbase + s * 16 + (lane >> 2);
            __half2 v0 = __floats2half2_rn(fmaxf(acc[s][nt][0] + bb0, 0.f),
                                           fmaxf(acc[s][nt][1] + bb1, 0.f));
            __half2 v1 = __floats2half2_rn(fmaxf(acc[s][nt][2] + bb0, 0.f),
                                           fmaxf(acc[s][nt][3] + bb1, 0.f));
            *reinterpret_cast<__half2*>(smem + OFF_A + r0 * (A_STRIDE_H * 2) + col * 2) = v0;
            *reinterpret_cast<__half2*>(smem + OFF_A + (r0 + 8) * (A_STRIDE_H * 2) + col * 2) = v1;
            acc[s][nt][0] = acc[s][nt][1] = acc[s][nt][2] = acc[s][nt][3] = 0.f;
        }
    }

    asm volatile("cp.async.wait_group 0;" ::: "memory");
    __syncthreads();                    // H visible + W2 staged

    // ---------------- Layer 2 ----------------
    run_gemm(sbase, Wsm, acc, lane, mbase, nbase);

    #pragma unroll
    for (int s = 0; s < 2; s++) {
        #pragma unroll
        for (int nt = 0; nt < 8; nt++) {
            int col = nbase + nt * 8 + 2 * (lane & 3);
            float bb0 = sB2[col], bb1 = sB2[col + 1];
            int r0 = mbase + s * 16 + (lane >> 2);
            int g0 = rowidx[r0];
            int g1 = rowidx[r0 + 8];
            if (g0 >= 0)
                *reinterpret_cast<float2*>(out + (size_t)g0 * DIN + col) =
                    make_float2(acc[s][nt][0] + bb0, acc[s][nt][1] + bb1);
            if (g1 >= 0)
                *reinterpret_cast<float2*>(out + (size_t)g1 * DIN + col) =
                    make_float2(acc[s][nt][2] + bb0, acc[s][nt][3] + bb1);
        }
    }
}

extern "C" void kernel_launch(void* const* d_in, const int* in_sizes, int n_in,
                              void* d_out, int out_size)
{
    const float* x     = (const float*)d_in[0];
    const float* W1    = (const float*)d_in[1];
    const float* b1    = (const float*)d_in[2];
    const float* W2    = (const float*)d_in[3];
    const float* b2    = (const float*)d_in[4];
    const int*   types = (const int*)  d_in[5];
    float*       out   = (float*)d_out;

    cudaFuncSetAttribute(mlp_kernel, cudaFuncAttributeMaxDynamicSharedMemorySize, SMEM_BYTES);

    prep_kernel<<<WELEMS / 256, 256>>>(W1, W2);
    scatter_kernel<<<NNODES / 256, 256>>>(types);
    mlp_kernel<<<MAXWORK, 256, SMEM_BYTES>>>(x, b1, b2, out);
}